// round 8
// baseline (speedup 1.0000x reference)
#include <cuda_runtime.h>

#define DD 64
#define HH 512
#define WW 512
#define W4 (WW / 4)
#define THRESH 0.5f

// 64 MB scratch (device global, allocation-free rule): W+H pooled volume,
// sign bit = "raw center equals its 9x9 WH-window max" flag.
__device__ float4 g_tmp[(size_t)DD * HH * W4];

#define TH1 19   // H rows per block in k1 -> 27 trips, FULLY unrolled
#define GY1 27   // ceil(512/19)
#define DSEG 16  // D outputs per thread in k2 -> 24 trips

__device__ __forceinline__ float4 vmax4(float4 a, float4 b) {
    return make_float4(fmaxf(a.x, b.x), fmaxf(a.y, b.y),
                       fmaxf(a.z, b.z), fmaxf(a.w, b.w));
}
__device__ __forceinline__ float4 vabs4(float4 a) {
    return make_float4(fabsf(a.x), fabsf(a.y), fabsf(a.z), fabsf(a.w));
}

// ---------------------------------------------------------------------------
// k1: 9-tap W max (tree) then 9-tap H max via prefix-pair scheme:
//   P2[j-1] = max(y[j-1], y[j]);  Q[j-3] = max(P2[j-3], P2[j-1]);
//   out[o]  = max(Q[o-4], Q[o], y[o+4])   (o = cursor-4)
// 4 fmax/lane/trip on the H axis. Shift chains renamed under full unroll.
// Sign bit of stored value = (whmax == raw center). Threshold deferred
// (raw values >= 0 so 0-padding exact). No smem/syncs.
// ---------------------------------------------------------------------------
__global__ void __launch_bounds__(128) k_wh(const float4* __restrict__ in) {
    const int t  = threadIdx.x;
    const int h0 = blockIdx.y * TH1;
    const int d  = blockIdx.z;
    const float4* base = in    + (size_t)d * HH * W4;
    float4*       tmpb = g_tmp + (size_t)d * HH * W4;

    const float4 z4 = make_float4(0.f, 0.f, 0.f, 0.f);
    float4 y1 = z4;                        // y[j-1]
    float4 p2a = z4, p2b = z4;             // P2[j-2], P2[j-3]
    float4 q1 = z4, q2 = z4, q3 = z4, q4 = z4, q5 = z4;  // Q[j-4..j-8]
    float4 c0 = z4, c1 = z4, c2 = z4, c3 = z4;           // raw center delay

#pragma unroll
    for (int hh = 0; hh < TH1 + 8; hh++) {   // cursor row j = hi
        const int hi = h0 - 4 + hh;
        const bool rowok = (hi >= 0) & (hi < HH);
        const float4* row = base + (size_t)hi * W4;

        float4 L = (rowok && t > 0)      ? row[t - 1] : z4;
        float4 M = rowok                 ? row[t]     : z4;
        float4 R = (rowok && t < W4 - 1) ? row[t + 1] : z4;

        // 9-tap W max: a0..a11 = L.xyzw M.xyzw R.xyzw, out_i = max(a[i..i+8])
        float c  = fmaxf(fmaxf(fmaxf(L.w, M.x), fmaxf(M.y, M.z)),
                         fmaxf(M.w, R.x));             // max(a3..a8)
        float u1 = fmaxf(L.y, L.z);                    // max(a1,a2)
        float u2 = fmaxf(R.y, R.z);                    // max(a9,a10)
        float4 y;
        y.x = fmaxf(fmaxf(c, L.x), u1);
        y.y = fmaxf(fmaxf(c, R.y), u1);
        y.z = fmaxf(fmaxf(c, L.z), u2);
        y.w = fmaxf(fmaxf(c, R.w), u2);

        // emit out row o = hi-4: max(Q[o-4]=q5, Q[o]=q1, y[o+4]=y)
        const int ho = hi - 4;
        if (hh >= 8 && ho < HH) {
            float4 m = vmax4(vmax4(q5, q1), y);
            // c3 = raw center row (hi-4) = output row
            float4 o;
            o.x = __uint_as_float(__float_as_uint(m.x) | ((m.x == c3.x) ? 0x80000000u : 0u));
            o.y = __uint_as_float(__float_as_uint(m.y) | ((m.y == c3.y) ? 0x80000000u : 0u));
            o.z = __uint_as_float(__float_as_uint(m.z) | ((m.z == c3.z) ? 0x80000000u : 0u));
            o.w = __uint_as_float(__float_as_uint(m.w) | ((m.w == c3.w) ? 0x80000000u : 0u));
            tmpb[(size_t)ho * W4 + t] = o;
        }

        // pipeline update (all renamed under full unroll)
        float4 p2n = vmax4(y1, y);        // P2[j-1]
        float4 qn  = vmax4(p2b, p2n);     // Q[j-3]
        q5 = q4; q4 = q3; q3 = q2; q2 = q1; q1 = qn;
        p2b = p2a; p2a = p2n;
        y1 = y;
        c3 = c2; c2 = c1; c1 = c0; c0 = M;
    }
}

// ---------------------------------------------------------------------------
// k2: 9-tap D max over |tmp| via the same prefix-pair scheme (abs folds into
// FMNMX modifiers), gate = (M > 0.5 && M == |center| && signbit(center)).
// No input re-read. Zero-init state = exact padding.
// grid: (HH*W4/128, DD/DSEG), block 128.
// ---------------------------------------------------------------------------
__global__ void __launch_bounds__(128) k_d(float4* __restrict__ out) {
    const size_t col   = (size_t)blockIdx.x * 128 + threadIdx.x;
    const int    d0    = blockIdx.y * DSEG;
    const size_t slice = (size_t)HH * W4;

    const float4 z4 = make_float4(0.f, 0.f, 0.f, 0.f);
    float4 a1 = z4;                        // |p|[j-1]
    float4 p2a = z4, p2b = z4;             // P2[j-2], P2[j-3]
    float4 q1 = z4, q2 = z4, q3 = z4, q4 = z4, q5 = z4;  // Q[j-4..j-8]
    float4 c0 = z4, c1 = z4, c2 = z4, c3 = z4;           // raw (signed) delay

#pragma unroll
    for (int di = 0; di < DSEG + 8; di++) {
        const int p = d0 + di - 4;              // cursor plane j
        float4 v = z4;
        if ((unsigned)p < DD) v = g_tmp[(size_t)p * slice + col];
        float4 a = vabs4(v);

        const int o = di - 8;                   // out plane = j-4
        if (o >= 0) {
            float4 m = vmax4(vmax4(q5, q1), a);
            const float4 cv = c3;               // raw center plane (j-4)
            float4 ov;
            ov.x = (m.x > THRESH && m.x == fabsf(cv.x) &&
                    (__float_as_uint(cv.x) & 0x80000000u)) ? m.x : 0.f;
            ov.y = (m.y > THRESH && m.y == fabsf(cv.y) &&
                    (__float_as_uint(cv.y) & 0x80000000u)) ? m.y : 0.f;
            ov.z = (m.z > THRESH && m.z == fabsf(cv.z) &&
                    (__float_as_uint(cv.z) & 0x80000000u)) ? m.z : 0.f;
            ov.w = (m.w > THRESH && m.w == fabsf(cv.w) &&
                    (__float_as_uint(cv.w) & 0x80000000u)) ? m.w : 0.f;
            out[(size_t)(d0 + o) * slice + col] = ov;
        }

        float4 p2n = vmax4(a1, a);
        float4 qn  = vmax4(p2b, p2n);
        q5 = q4; q4 = q3; q3 = q2; q2 = q1; q1 = qn;
        p2b = p2a; p2a = p2n;
        a1 = a;
        c3 = c2; c2 = c1; c1 = c0; c0 = v;
    }
}

extern "C" void kernel_launch(void* const* d_in, const int* in_sizes, int n_in,
                              void* d_out, int out_size) {
    const float4* in  = (const float4*)d_in[0];
    float4*       out = (float4*)d_out;

    dim3 g1(1, GY1, DD);                 // 1728 blocks
    k_wh<<<g1, 128>>>(in);

    dim3 g2((HH * W4) / 128, DD / DSEG); // 2048 blocks
    k_d<<<g2, 128>>>(out);
}

// round 9
// speedup vs baseline: 1.1938x; 1.1938x over previous
#include <cuda_runtime.h>

#define DD 64
#define HH 512
#define WW 512
#define W4 (WW / 4)
#define THRESH 0.5f

// 64 MB scratch (device global, allocation-free rule): W+H pooled volume,
// sign bit = "raw center equals its 9x9 WH-window max" flag.
__device__ float4 g_tmp[(size_t)DD * HH * W4];

#define TH1 19   // H rows per block in k1 -> 27 trips (3 full segments of 9)
#define GY1 27   // ceil(512/19)
#define DSEG 16  // D outputs per thread in k2 -> 24 trips

__device__ __forceinline__ float4 vmax4(float4 a, float4 b) {
    return make_float4(fmaxf(a.x, b.x), fmaxf(a.y, b.y),
                       fmaxf(a.z, b.z), fmaxf(a.w, b.w));
}
__device__ __forceinline__ float4 vabs4(float4 a) {
    return make_float4(fabsf(a.x), fabsf(a.y), fabsf(a.z), fabsf(a.w));
}

// ---------------------------------------------------------------------------
// k1: 9-tap W max (tree), then 9-tap H max via van Herk / Gil-Werman:
// segments of 9 trips; at trip%9==8 convert ring in place to suffix maxes
// (8 fmax, amortized 0.9/trip); running prefix P (reset at segment start);
// out[o] = max(S[o-4], P) with r = cursor. Ring slot for S[l] is consumed at
// trip l+8, overwritten at l+9 (just in time). Sign bit of stored value =
// (whmax == raw center). Threshold deferred (values >= 0 -> 0-pad exact).
// ---------------------------------------------------------------------------
__global__ void __launch_bounds__(128) k_wh(const float4* __restrict__ in) {
    const int t  = threadIdx.x;
    const int h0 = blockIdx.y * TH1;
    const int d  = blockIdx.z;
    const float4* base = in    + (size_t)d * HH * W4;
    float4*       tmpb = g_tmp + (size_t)d * HH * W4;

    const float4 z4 = make_float4(0.f, 0.f, 0.f, 0.f);
    float4 ring[9];
    float4 P = z4;
    float4 c0 = z4, c1 = z4, c2 = z4, c3 = z4;   // raw-center delay chain

#pragma unroll
    for (int hh = 0; hh < TH1 + 8; hh++) {       // 27 trips, fully unrolled
        const int hi = h0 - 4 + hh;
        const bool rowok = (hi >= 0) & (hi < HH);
        const float4* row = base + (size_t)hi * W4;

        float4 L = (rowok && t > 0)      ? row[t - 1] : z4;
        float4 M = rowok                 ? row[t]     : z4;
        float4 R = (rowok && t < W4 - 1) ? row[t + 1] : z4;

        // 9-tap W max: a0..a11 = L.xyzw M.xyzw R.xyzw, out_i = max(a[i..i+8])
        float c  = fmaxf(fmaxf(fmaxf(L.w, M.x), fmaxf(M.y, M.z)),
                         fmaxf(M.w, R.x));       // max(a3..a8)
        float u1 = fmaxf(L.y, L.z);
        float u2 = fmaxf(R.y, R.z);
        float4 y;
        y.x = fmaxf(fmaxf(c, L.x), u1);
        y.y = fmaxf(fmaxf(c, R.y), u1);
        y.z = fmaxf(fmaxf(c, L.z), u2);
        y.w = fmaxf(fmaxf(c, R.w), u2);

        ring[hh % 9] = y;                        // static index (full unroll)
        P = (hh % 9 == 0) ? y : vmax4(P, y);     // prefix within segment

        if (hh % 9 == 8) {                       // segment end: in-place suffix
#pragma unroll
            for (int i = 7; i >= 0; i--) ring[i] = vmax4(ring[i], ring[i + 1]);
        }

        const int ho = h0 + hh - 8;              // output row (cursor-4)
        if (hh >= 8 && ho < HH) {
            float4 m = vmax4(ring[(hh - 8) % 9], P);
            float4 o;   // c3 = raw center row (= output row)
            o.x = __uint_as_float(__float_as_uint(m.x) | ((m.x == c3.x) ? 0x80000000u : 0u));
            o.y = __uint_as_float(__float_as_uint(m.y) | ((m.y == c3.y) ? 0x80000000u : 0u));
            o.z = __uint_as_float(__float_as_uint(m.z) | ((m.z == c3.z) ? 0x80000000u : 0u));
            o.w = __uint_as_float(__float_as_uint(m.w) | ((m.w == c3.w) ? 0x80000000u : 0u));
            tmpb[(size_t)ho * W4 + t] = o;
        }

        c3 = c2; c2 = c1; c1 = c0; c0 = M;       // renamed under full unroll
    }
}

// ---------------------------------------------------------------------------
// k2: 9-tap D max over |tmp| via the same van Herk scheme (abs folds into
// FMNMX modifiers). Gate = (M > 0.5 && M == |center| && signbit(center)).
// Signed center comes from a 4-deep delay chain. No input re-read.
// Suffix passes at di=8,17 only (last partial segment feeds P side only).
// grid: (HH*W4/128, DD/DSEG), block 128.
// ---------------------------------------------------------------------------
__global__ void __launch_bounds__(128) k_d(float4* __restrict__ out) {
    const size_t col   = (size_t)blockIdx.x * 128 + threadIdx.x;
    const int    d0    = blockIdx.y * DSEG;
    const size_t slice = (size_t)HH * W4;

    const float4 z4 = make_float4(0.f, 0.f, 0.f, 0.f);
    float4 ring[9];
    float4 P = z4;
    float4 c0 = z4, c1 = z4, c2 = z4, c3 = z4;   // signed raw delay chain

#pragma unroll
    for (int di = 0; di < DSEG + 8; di++) {      // 24 trips, fully unrolled
        const int p = d0 + di - 4;               // cursor plane
        float4 v = z4;
        if ((unsigned)p < DD) v = g_tmp[(size_t)p * slice + col];
        float4 a = vabs4(v);

        ring[di % 9] = a;
        P = (di % 9 == 0) ? a : vmax4(P, a);

        if (di % 9 == 8) {                       // di = 8, 17
#pragma unroll
            for (int i = 7; i >= 0; i--) ring[i] = vmax4(ring[i], ring[i + 1]);
        }

        const int o = di - 8;                    // output plane offset
        if (o >= 0) {
            float4 m = vmax4(ring[(di - 8) % 9], P);
            const float4 cv = c3;                // signed center plane
            float4 ov;
            ov.x = (m.x > THRESH && m.x == fabsf(cv.x) &&
                    (__float_as_uint(cv.x) & 0x80000000u)) ? m.x : 0.f;
            ov.y = (m.y > THRESH && m.y == fabsf(cv.y) &&
                    (__float_as_uint(cv.y) & 0x80000000u)) ? m.y : 0.f;
            ov.z = (m.z > THRESH && m.z == fabsf(cv.z) &&
                    (__float_as_uint(cv.z) & 0x80000000u)) ? m.z : 0.f;
            ov.w = (m.w > THRESH && m.w == fabsf(cv.w) &&
                    (__float_as_uint(cv.w) & 0x80000000u)) ? m.w : 0.f;
            out[(size_t)(d0 + o) * slice + col] = ov;
        }

        c3 = c2; c2 = c1; c1 = c0; c0 = v;
    }
}

extern "C" void kernel_launch(void* const* d_in, const int* in_sizes, int n_in,
                              void* d_out, int out_size) {
    const float4* in  = (const float4*)d_in[0];
    float4*       out = (float4*)d_out;

    dim3 g1(1, GY1, DD);                 // 1728 blocks
    k_wh<<<g1, 128>>>(in);

    dim3 g2((HH * W4) / 128, DD / DSEG); // 2048 blocks
    k_d<<<g2, 128>>>(out);
}